// round 12
// baseline (speedup 1.0000x reference)
#include <cuda_runtime.h>
#include <cstdint>

// C4TransformerVM: exact 4-byte ripple-carry add over one-hot byte encodings.
// softmax(temp=100) over integer logit gaps makes every intermediate one-hot
// to ~3.6e-44 in fp32 -> decode (argmax), uint32 add (final carry discarded),
// re-encode one-hot. Irreducible traffic: 256 MB read + 128 MB write.
//
// History:
//  R3 fused regs=40: 69% DRAM.  R4 split: regression.  R5 lb(256,3): 77.6%.
//  R6 zero-store overlap: 79.2%.  R7 persistent: regression.  R8 64-thr: =.
//  R9 TMA stores: =.  R10 occ 41%: =.  R11 v8 (256-bit) ld/st: 54.75us
//     kernel @ 80.3% DRAM (6567 GB/s) <- best; wavefront-halving confirmed
//     (L1 45->34%).
//  R12: restore streaming cache hints lost in the v8 rewrite (.cs on all
//       stores, L2::evict_first on loads) so the use-once read/write streams
//       stop competing for L2 residency.

__device__ __forceinline__ void ldg256(const float* p, float4& lo, float4& hi) {
    asm volatile(
        "ld.global.nc.L2::evict_first.v8.f32 {%0,%1,%2,%3,%4,%5,%6,%7}, [%8];"
        : "=f"(lo.x), "=f"(lo.y), "=f"(lo.z), "=f"(lo.w),
          "=f"(hi.x), "=f"(hi.y), "=f"(hi.z), "=f"(hi.w)
        : "l"(p));
}

__device__ __forceinline__ void stg256_zero_cs(float* p) {
    asm volatile(
        "st.global.cs.v8.f32 [%0], {%1,%1,%1,%1,%1,%1,%1,%1};"
        :: "l"(p), "f"(0.0f) : "memory");
}

__device__ __forceinline__ uint32_t scan8_mask(float4 v0, float4 v1, int base, int sh) {
    uint32_t idx = 0;
    if (v0.x > 0.5f) idx = (uint32_t)(base + 0);
    if (v0.y > 0.5f) idx = (uint32_t)(base + 1);
    if (v0.z > 0.5f) idx = (uint32_t)(base + 2);
    if (v0.w > 0.5f) idx = (uint32_t)(base + 3);
    if (v1.x > 0.5f) idx = (uint32_t)(base + 4);
    if (v1.y > 0.5f) idx = (uint32_t)(base + 5);
    if (v1.z > 0.5f) idx = (uint32_t)(base + 6);
    if (v1.w > 0.5f) idx = (uint32_t)(base + 7);
    return idx << sh;
}

__global__ __launch_bounds__(256, 3) void neural_alu_add_kernel(
    const float* __restrict__ a,
    const float* __restrict__ b,
    float* __restrict__ out,
    int N)
{
    const int warp_id = (blockIdx.x * blockDim.x + threadIdx.x) >> 5;
    const int lane = threadIdx.x & 31;
    if (warp_id >= N) return;
    const size_t n = (size_t)warp_id;
    const int base = lane * 8;

    // ---- Phase 1: 8x 256-bit loads (each lane: 8 contiguous floats/row).
    float4 va[8], vb[8];
#pragma unroll
    for (int i = 0; i < 4; i++) {
        const float* ra = a + ((size_t)i * N + n) * 256 + base;
        const float* rb = b + ((size_t)i * N + n) * 256 + base;
        ldg256(ra, va[2 * i], va[2 * i + 1]);
        ldg256(rb, vb[2 * i], vb[2 * i + 1]);
    }

    // ---- Phase 2: zero all 4 output rows with streaming 256-bit stores
    // (independent of the loads; drains while reads are in flight).
#pragma unroll
    for (int i = 0; i < 4; i++) {
        stg256_zero_cs(out + ((size_t)i * N + n) * 256 + base);
    }

    // ---- Phase 3: decode. Pack byte-i index into bits [8i,8i+8); at most
    // one lane nonzero per byte (hot index 0 => all-zero, also correct), so
    // one OR-reduction per operand reconstructs the 32-bit word.
    uint32_t Ap = 0, Bp = 0;
#pragma unroll
    for (int i = 0; i < 4; i++) {
        Ap |= scan8_mask(va[2 * i], va[2 * i + 1], base, 8 * i);
        Bp |= scan8_mask(vb[2 * i], vb[2 * i + 1], base, 8 * i);
    }
    const uint32_t A = __reduce_or_sync(0xffffffffu, Ap);
    const uint32_t B = __reduce_or_sync(0xffffffffu, Bp);

    const uint32_t S = A + B;   // carry out of byte 3 discarded

    // ---- Phase 4: owning lane patches the hot element of each row. Same
    // thread + same address range as its zero store -> program order
    // guarantees the 1.0 lands last.
#pragma unroll
    for (int i = 0; i < 4; i++) {
        const int r = (int)((S >> (8 * i)) & 255u);
        if ((r >> 3) == lane) {
            __stcs(out + ((size_t)i * N + n) * 256 + r, 1.0f);
        }
    }
}

extern "C" void kernel_launch(void* const* d_in, const int* in_sizes, int n_in,
                              void* d_out, int out_size) {
    const float* a = (const float*)d_in[0];   // [4, N, 256] one-hot
    const float* b = (const float*)d_in[1];   // [4, N, 256] one-hot
    float* out = (float*)d_out;               // [4, N, 256]
    const int N = in_sizes[0] / (4 * 256);

    const int threads = 256;                  // 8 warps/block, 1 warp per n
    const int blocks = (N * 32 + threads - 1) / threads;
    neural_alu_add_kernel<<<blocks, threads>>>(a, b, out, N);
}

// round 13
// speedup vs baseline: 1.0597x; 1.0597x over previous
#include <cuda_runtime.h>
#include <cstdint>

// C4TransformerVM: exact 4-byte ripple-carry add over one-hot byte encodings.
// softmax(temp=100) over integer logit gaps makes every intermediate one-hot
// to ~3.6e-44 in fp32 -> decode (argmax), uint32 add (final carry discarded),
// re-encode one-hot. Irreducible traffic: 256 MB read + 128 MB write.
//
// Final configuration (R11, best kernel 54.75us @ 6567 GB/s = 82% of spec):
//  - fused single kernel, 1 warp per n, launch_bounds(256,3) for MLP
//  - Blackwell 256-bit ld/st (v8.f32): halves L1tex wavefronts + instr count
//  - zero-store overlap (stores independent of in-flight loads) + owner-lane
//    1.0 patch (same-thread same-address program order)
//  - DEFAULT cache policies: R12 proved .cs / L2::evict_first REGRESS (-2.4us)
// Falsified along the way: split kernels (R4), persistent grid (R7), small
// CTAs (R8), TMA bulk stores (R9), occ 41% (R10), cache hints (R12).

__device__ __forceinline__ void ldg256(const float* p, float4& lo, float4& hi) {
    asm volatile(
        "ld.global.nc.v8.f32 {%0,%1,%2,%3,%4,%5,%6,%7}, [%8];"
        : "=f"(lo.x), "=f"(lo.y), "=f"(lo.z), "=f"(lo.w),
          "=f"(hi.x), "=f"(hi.y), "=f"(hi.z), "=f"(hi.w)
        : "l"(p));
}

__device__ __forceinline__ void stg256_zero(float* p) {
    asm volatile(
        "st.global.v8.f32 [%0], {%1,%1,%1,%1,%1,%1,%1,%1};"
        :: "l"(p), "f"(0.0f) : "memory");
}

__device__ __forceinline__ uint32_t scan8_mask(float4 v0, float4 v1, int base, int sh) {
    uint32_t idx = 0;
    if (v0.x > 0.5f) idx = (uint32_t)(base + 0);
    if (v0.y > 0.5f) idx = (uint32_t)(base + 1);
    if (v0.z > 0.5f) idx = (uint32_t)(base + 2);
    if (v0.w > 0.5f) idx = (uint32_t)(base + 3);
    if (v1.x > 0.5f) idx = (uint32_t)(base + 4);
    if (v1.y > 0.5f) idx = (uint32_t)(base + 5);
    if (v1.z > 0.5f) idx = (uint32_t)(base + 6);
    if (v1.w > 0.5f) idx = (uint32_t)(base + 7);
    return idx << sh;
}

__global__ __launch_bounds__(256, 3) void neural_alu_add_kernel(
    const float* __restrict__ a,
    const float* __restrict__ b,
    float* __restrict__ out,
    int N)
{
    const int warp_id = (blockIdx.x * blockDim.x + threadIdx.x) >> 5;
    const int lane = threadIdx.x & 31;
    if (warp_id >= N) return;
    const size_t n = (size_t)warp_id;
    const int base = lane * 8;

    // ---- Phase 1: 8x 256-bit loads (each lane: 8 contiguous floats/row).
    float4 va[8], vb[8];
#pragma unroll
    for (int i = 0; i < 4; i++) {
        const float* ra = a + ((size_t)i * N + n) * 256 + base;
        const float* rb = b + ((size_t)i * N + n) * 256 + base;
        ldg256(ra, va[2 * i], va[2 * i + 1]);
        ldg256(rb, vb[2 * i], vb[2 * i + 1]);
    }

    // ---- Phase 2: zero all 4 output rows with 256-bit stores (independent
    // of the loads; drains while reads are in flight).
#pragma unroll
    for (int i = 0; i < 4; i++) {
        stg256_zero(out + ((size_t)i * N + n) * 256 + base);
    }

    // ---- Phase 3: decode. Pack byte-i index into bits [8i,8i+8); at most
    // one lane nonzero per byte (hot index 0 => all-zero, also correct), so
    // one OR-reduction per operand reconstructs the 32-bit word.
    uint32_t Ap = 0, Bp = 0;
#pragma unroll
    for (int i = 0; i < 4; i++) {
        Ap |= scan8_mask(va[2 * i], va[2 * i + 1], base, 8 * i);
        Bp |= scan8_mask(vb[2 * i], vb[2 * i + 1], base, 8 * i);
    }
    const uint32_t A = __reduce_or_sync(0xffffffffu, Ap);
    const uint32_t B = __reduce_or_sync(0xffffffffu, Bp);

    const uint32_t S = A + B;   // carry out of byte 3 discarded

    // ---- Phase 4: owning lane patches the hot element of each row. Same
    // thread + same address range as its zero store -> program order
    // guarantees the 1.0 lands last.
#pragma unroll
    for (int i = 0; i < 4; i++) {
        const int r = (int)((S >> (8 * i)) & 255u);
        if ((r >> 3) == lane) {
            out[((size_t)i * N + n) * 256 + r] = 1.0f;
        }
    }
}

extern "C" void kernel_launch(void* const* d_in, const int* in_sizes, int n_in,
                              void* d_out, int out_size) {
    const float* a = (const float*)d_in[0];   // [4, N, 256] one-hot
    const float* b = (const float*)d_in[1];   // [4, N, 256] one-hot
    float* out = (float*)d_out;               // [4, N, 256]
    const int N = in_sizes[0] / (4 * 256);

    const int threads = 256;                  // 8 warps/block, 1 warp per n
    const int blocks = (N * 32 + threads - 1) / threads;
    neural_alu_add_kernel<<<blocks, threads>>>(a, b, out, N);
}

// round 14
// speedup vs baseline: 1.0640x; 1.0040x over previous
#include <cuda_runtime.h>
#include <cstdint>

// C4TransformerVM: exact 4-byte ripple-carry add over one-hot byte encodings.
// softmax(temp=100) over integer logit gaps makes every intermediate one-hot
// to ~3.6e-44 in fp32 -> decode (argmax), uint32 add (final carry discarded),
// re-encode one-hot. Irreducible traffic: 256 MB read + 128 MB write.
//
// CONVERGED configuration (reproduced twice: 54.75us / 54.43us kernel,
// 6567 / 6572 GB/s = 82% of spec):
//  - fused single kernel, 1 warp per n, launch_bounds(256,3) -> regs=78,
//    all 8 v8-loads in flight (MLP win: DRAM 69% -> 78%)
//  - Blackwell 256-bit ld/st (v8.f32): halves L1tex wavefronts (L1 45->34%,
//    DRAM 78% -> 80.4%)
//  - zero-store overlap (stores independent of in-flight loads) + owner-lane
//    1.0 patch (same-thread same-address program order; patch merges into
//    the L2-dirty sector -> no extra DRAM writeback)
//  - DEFAULT cache policies (.cs / L2::evict_first measured -2.4us)
// Falsified: split kernels (R4), persistent grid (R7), 64-thr CTAs (R8),
// TMA bulk stores (R9), occ 41% (R10), streaming hints (R12).

__device__ __forceinline__ void ldg256(const float* p, float4& lo, float4& hi) {
    asm volatile(
        "ld.global.nc.v8.f32 {%0,%1,%2,%3,%4,%5,%6,%7}, [%8];"
        : "=f"(lo.x), "=f"(lo.y), "=f"(lo.z), "=f"(lo.w),
          "=f"(hi.x), "=f"(hi.y), "=f"(hi.z), "=f"(hi.w)
        : "l"(p));
}

__device__ __forceinline__ void stg256_zero(float* p) {
    asm volatile(
        "st.global.v8.f32 [%0], {%1,%1,%1,%1,%1,%1,%1,%1};"
        :: "l"(p), "f"(0.0f) : "memory");
}

__device__ __forceinline__ uint32_t scan8_mask(float4 v0, float4 v1, int base, int sh) {
    uint32_t idx = 0;
    if (v0.x > 0.5f) idx = (uint32_t)(base + 0);
    if (v0.y > 0.5f) idx = (uint32_t)(base + 1);
    if (v0.z > 0.5f) idx = (uint32_t)(base + 2);
    if (v0.w > 0.5f) idx = (uint32_t)(base + 3);
    if (v1.x > 0.5f) idx = (uint32_t)(base + 4);
    if (v1.y > 0.5f) idx = (uint32_t)(base + 5);
    if (v1.z > 0.5f) idx = (uint32_t)(base + 6);
    if (v1.w > 0.5f) idx = (uint32_t)(base + 7);
    return idx << sh;
}

__global__ __launch_bounds__(256, 3) void neural_alu_add_kernel(
    const float* __restrict__ a,
    const float* __restrict__ b,
    float* __restrict__ out,
    int N)
{
    const int warp_id = (blockIdx.x * blockDim.x + threadIdx.x) >> 5;
    const int lane = threadIdx.x & 31;
    if (warp_id >= N) return;
    const size_t n = (size_t)warp_id;
    const int base = lane * 8;

    // ---- Phase 1: 8x 256-bit loads (each lane: 8 contiguous floats/row).
    float4 va[8], vb[8];
#pragma unroll
    for (int i = 0; i < 4; i++) {
        const float* ra = a + ((size_t)i * N + n) * 256 + base;
        const float* rb = b + ((size_t)i * N + n) * 256 + base;
        ldg256(ra, va[2 * i], va[2 * i + 1]);
        ldg256(rb, vb[2 * i], vb[2 * i + 1]);
    }

    // ---- Phase 2: zero all 4 output rows with 256-bit stores (independent
    // of the loads; drains while reads are in flight).
#pragma unroll
    for (int i = 0; i < 4; i++) {
        stg256_zero(out + ((size_t)i * N + n) * 256 + base);
    }

    // ---- Phase 3: decode. Pack byte-i index into bits [8i,8i+8); at most
    // one lane nonzero per byte (hot index 0 => all-zero, also correct), so
    // one OR-reduction per operand reconstructs the 32-bit word.
    uint32_t Ap = 0, Bp = 0;
#pragma unroll
    for (int i = 0; i < 4; i++) {
        Ap |= scan8_mask(va[2 * i], va[2 * i + 1], base, 8 * i);
        Bp |= scan8_mask(vb[2 * i], vb[2 * i + 1], base, 8 * i);
    }
    const uint32_t A = __reduce_or_sync(0xffffffffu, Ap);
    const uint32_t B = __reduce_or_sync(0xffffffffu, Bp);

    const uint32_t S = A + B;   // carry out of byte 3 discarded

    // ---- Phase 4: owning lane patches the hot element of each row. Same
    // thread + same address range as its zero store -> program order
    // guarantees the 1.0 lands last; merges in L2, no extra DRAM traffic.
#pragma unroll
    for (int i = 0; i < 4; i++) {
        const int r = (int)((S >> (8 * i)) & 255u);
        if ((r >> 3) == lane) {
            out[((size_t)i * N + n) * 256 + r] = 1.0f;
        }
    }
}

extern "C" void kernel_launch(void* const* d_in, const int* in_sizes, int n_in,
                              void* d_out, int out_size) {
    const float* a = (const float*)d_in[0];   // [4, N, 256] one-hot
    const float* b = (const float*)d_in[1];   // [4, N, 256] one-hot
    float* out = (float*)d_out;               // [4, N, 256]
    const int N = in_sizes[0] / (4 * 256);

    const int threads = 256;                  // 8 warps/block, 1 warp per n
    const int blocks = (N * 32 + threads - 1) / threads;
    neural_alu_add_kernel<<<blocks, threads>>>(a, b, out, N);
}